// round 4
// baseline (speedup 1.0000x reference)
#include <cuda_runtime.h>
#include <cstdint>

// Problem constants
#define NN 50000
#define FF 64
#define HH 128

// ---------------- device scratch (static globals, no cudaMalloc) -------------
__device__ float g_deg[NN];
__device__ float g_dinv[NN];
__device__ float g_AX[(size_t)NN * FF];          // aggregated X  (N x 64)
__device__ float g_ZR[(size_t)NN * 256];         // Z cols 0..127, R cols 128..255
__device__ float g_reluh[(size_t)NN * HH];       // relu(h)
// permuted tf32 weights: 6 blocks of 192x64 (gate GEMMs) + 1 block of 128x64 (Lout)
__device__ uint32_t g_Bp[6 * 12288 + 8192];
__device__ float g_bcat[384];                    // packed gate biases

// ---------------- helpers -----------------------------------------------------
__device__ __forceinline__ uint32_t f2tf32(float x) {
    uint32_t r;
    asm("cvt.rna.tf32.f32 %0, %1;" : "=r"(r) : "f"(x));
    return r;
}
__device__ __forceinline__ void mma_tf32(float* c, const uint32_t* a, const uint32_t* b) {
    asm volatile(
        "mma.sync.aligned.m16n8k8.row.col.f32.tf32.tf32.f32 "
        "{%0,%1,%2,%3}, {%4,%5,%6,%7}, {%8,%9}, {%0,%1,%2,%3};"
        : "+f"(c[0]), "+f"(c[1]), "+f"(c[2]), "+f"(c[3])
        : "r"(a[0]), "r"(a[1]), "r"(a[2]), "r"(a[3]), "r"(b[0]), "r"(b[1]));
}
#define KSROT(l, ks) ((((l) + (ks) * 5)) & 31)

// ---------------- weight packing ---------------------------------------------
// Permuted-B element placement (matches GEMM fragment reads):
//   block = col/64, c = (col/8)%8, gid = col%8
//   ks = k/8, tig = k%3.. (k&3), jj = (k>>2)&1, lane = gid*4+tig
//   idx = block*(K*64) + ((ks*8+c)*32+lane)*2 + jj
__global__ void k_pack(const float* Wz, const float* bz,
                       const float* Wr, const float* br,
                       const float* Wh, const float* bh,
                       const float* Lz, const float* Lzb,
                       const float* Lr, const float* Lrb,
                       const float* Lh, const float* Lhb,
                       const float* LoW) {
    int idx = blockIdx.x * blockDim.x + threadIdx.x;
    const int T1 = 384 * 192;            // gate weights
    const int T2 = T1 + 64 * 128;        // + Lout
    if (idx < T1) {
        int j = idx / 192, k = idx % 192;     // j = output col (0..383), k = input dim
        int g = j >> 7;
        int jj = j & 127;
        const float* W = (g == 0) ? Wz : (g == 1) ? Wr : Wh;
        const float* L = (g == 0) ? Lz : (g == 1) ? Lr : Lh;
        float v;
        if (k < 64) {
            v = 0.f;
            #pragma unroll 8
            for (int t = 0; t < 128; t++) v += W[k * 128 + t] * L[t * 128 + jj];
        } else {
            v = L[(128 + (k - 64)) * 128 + jj];
        }
        int blk = j >> 6, c = (j >> 3) & 7, gid = j & 7;
        int ks = k >> 3, tig = k & 3, jjj = (k >> 2) & 1;
        int lane = gid * 4 + tig;
        g_Bp[blk * 12288 + ((ks * 8 + c) * 32 + lane) * 2 + jjj] = f2tf32(v);
    } else if (idx < T2) {
        int u = idx - T1;
        int n = u >> 7, k = u & 127;          // Lout: col n (0..63), k (0..127)
        float v = LoW[k * 64 + n];
        int c = n >> 3, gid = n & 7;
        int ks = k >> 3, tig = k & 3, jjj = (k >> 2) & 1;
        int lane = gid * 4 + tig;
        g_Bp[6 * 12288 + ((ks * 8 + c) * 32 + lane) * 2 + jjj] = f2tf32(v);
    } else if (idx < T2 + 384) {
        int j = idx - T2;
        int g = j >> 7;
        int jj = j & 127;
        const float* bg = (g == 0) ? bz : (g == 1) ? br : bh;
        const float* L  = (g == 0) ? Lz : (g == 1) ? Lr : Lh;
        const float* Lb = (g == 0) ? Lzb : (g == 1) ? Lrb : Lhb;
        float v = Lb[jj];
        for (int t = 0; t < 128; t++) v += bg[t] * L[t * 128 + jj];
        g_bcat[j] = v;
    }
}

// ---------------- degree / normalization -------------------------------------
__global__ void k_deg(const int* ei, const float* ew, int E) {
    int e = blockIdx.x * blockDim.x + threadIdx.x;
    if (e < E) atomicAdd(&g_deg[ei[E + e]], ew[e]);
}

// fused: dinv = rsqrt(deg+1), reset deg (for next graph replay), AX self-loop init
__global__ void k_dinvax(const float* __restrict__ X) {
    int tid = blockIdx.x * blockDim.x + threadIdx.x;
    if (tid >= NN * 16) return;
    int i = tid >> 4, q = tid & 15;
    float d  = g_deg[i] + 1.0f;       // self-loop weight 1
    float di = rsqrtf(d);
    __syncwarp();
    if (q == 0) { g_dinv[i] = di; g_deg[i] = 0.f; }
    float s = di * di;
    float4 x = reinterpret_cast<const float4*>(X + (size_t)i * 64)[q];
    float4 v = make_float4(x.x * s, x.y * s, x.z * s, x.w * s);
    reinterpret_cast<float4*>(g_AX + (size_t)i * 64)[q] = v;
}

// Edge scatter: AX[dst] += dinv[src]*w*dinv[dst] * X[src]   (16 threads/edge)
__global__ void k_agg(const int* __restrict__ ei, const float* __restrict__ ew,
                      const float* __restrict__ X, int E) {
    int tid = blockIdx.x * blockDim.x + threadIdx.x;
    int e = tid >> 4;
    if (e >= E) return;
    int q = tid & 15;
    int s = ei[e];
    int d = ei[E + e];
    float norm = g_dinv[s] * ew[e] * g_dinv[d];
    float4 x = reinterpret_cast<const float4*>(X + (size_t)s * 64)[q];
    float* p = g_AX + (size_t)d * 64 + q * 4;
    asm volatile("red.global.add.v4.f32 [%0], {%1, %2, %3, %4};"
                 :: "l"(p), "f"(x.x * norm), "f"(x.y * norm),
                    "f"(x.z * norm), "f"(x.w * norm)
                 : "memory");
}

// ---------------- tf32 tensor-core GEMM, fragment-major smem -----------------
// Block tile 128 x 64, 8 warps, warp tile 32x32. Whole-K B in smem (copied
// from pre-permuted global), A filled in 2 K-chunks.
// mode 0: sigmoid -> out0 stride 256 (Z,R)
// mode 1: tanh + GRU -> out0 = h (stride 128), out1 = relu(h)
// mode 2: plain -> out0 stride 64
template <int K1T, int K2T>
__global__ void __launch_bounds__(256)
gemm_tc(const float* __restrict__ A1,
        const float* __restrict__ A2,
        const float* __restrict__ Rbuf,
        const uint32_t* __restrict__ Bp,
        const float* __restrict__ bias,
        int mode,
        const float* __restrict__ Zbuf,
        const float* __restrict__ Hs,
        float* __restrict__ out0,
        float* __restrict__ out1) {
    constexpr int K   = K1T + K2T;
    constexpr int KCH = K / 2;          // A chunk depth
    constexpr int Q4  = KCH / 4;        // float4 per A row per chunk
    extern __shared__ uint32_t smem[];
    uint32_t* As = smem;                // 128*KCH words (fragment-major, rotated)
    uint32_t* Bs = smem + 128 * KCH;    // 64*K words (fragment-major)

    const int t    = threadIdx.x;
    const int lane = t & 31;
    const int wid  = t >> 5;
    const int warpRow = wid & 3;
    const int warpCol = wid >> 2;
    const int blockRow = blockIdx.x * 128;
    const int colGrp   = blockIdx.y * 64;

    // ---- B copy: pre-permuted tf32 weights, straight vector copy ----
    {
        const uint4* src = (const uint4*)(Bp + (size_t)blockIdx.y * (K * 64));
        uint4* dst = (uint4*)Bs;
        constexpr int cnt = (K * 64) / 4;
        #pragma unroll
        for (int i = 0; i < cnt / 256; i++) dst[t + i * 256] = src[t + i * 256];
    }

    float acc[2][4][4];
    #pragma unroll
    for (int mi = 0; mi < 2; mi++)
        #pragma unroll
        for (int ni = 0; ni < 4; ni++)
            #pragma unroll
            for (int c = 0; c < 4; c++) acc[mi][ni][c] = 0.f;

    #pragma unroll
    for (int ch = 0; ch < 2; ch++) {
        if (ch) __syncthreads();   // protect As reuse
        // ---- A fill (chunk): scatter into fragment-major layout ----
        #pragma unroll
        for (int it = 0; it < (128 * Q4) / 256; it++) {
            int i = t + it * 256;
            int row = i / Q4;
            int kl  = (i - row * Q4) * 4;
            int kg  = ch * KCH + kl;
            int grow = blockRow + row;
            float4 v = make_float4(0.f, 0.f, 0.f, 0.f);
            if (grow < NN) {
                if (kg < K1T) {
                    v = *(const float4*)(A1 + (size_t)grow * K1T + kg);
                } else if (K2T > 0) {
                    int k2 = kg - K1T;
                    v = *(const float4*)(A2 + (size_t)grow * K2T + k2);
                    if (Rbuf) {
                        float4 r = *(const float4*)(Rbuf + (size_t)grow * 256 + 128 + k2);
                        v.x *= r.x; v.y *= r.y; v.z *= r.z; v.w *= r.w;
                    }
                }
            }
            uint32_t w[4] = {f2tf32(v.x), f2tf32(v.y), f2tf32(v.z), f2tf32(v.w)};
            int mt  = row >> 4;
            int gid = row & 7;
            int jr  = (row >> 3) & 1;
            #pragma unroll
            for (int e = 0; e < 4; e++) {
                int kk  = kl + e;
                int ksl = kk >> 3;
                int jc  = (kk >> 2) & 1;
                int tig = kk & 3;
                int l   = gid * 4 + tig;
                As[(((ksl * 8 + mt) * 32) + KSROT(l, ksl)) * 4 + jr + 2 * jc] = w[e];
            }
        }
        __syncthreads();

        // ---- mainloop over this chunk: 2 LDS.128 + 4 LDS.64 + 8 MMA / kstep ----
        #pragma unroll
        for (int ksl = 0; ksl < KCH / 8; ksl++) {
            const int ksg = ch * (KCH / 8) + ksl;
            uint32_t a[2][4];
            #pragma unroll
            for (int mi = 0; mi < 2; mi++) {
                int mt = warpRow * 2 + mi;
                uint4 av = *(const uint4*)&As[((ksl * 8 + mt) * 32 + KSROT(lane, ksl)) * 4];
                a[mi][0] = av.x; a[mi][1] = av.y; a[mi][2] = av.z; a[mi][3] = av.w;
            }
            uint32_t b[4][2];
            #pragma unroll
            for (int ni = 0; ni < 4; ni++) {
                int c = warpCol * 4 + ni;
                uint2 bv = *(const uint2*)&Bs[((ksg * 8 + c) * 32 + lane) * 2];
                b[ni][0] = bv.x; b[ni][1] = bv.y;
            }
            #pragma unroll
            for (int mi = 0; mi < 2; mi++)
                #pragma unroll
                for (int ni = 0; ni < 4; ni++)
                    mma_tf32(acc[mi][ni], a[mi], b[ni]);
        }
    }

    // ---- epilogue (float2-vectorized stores) ----
    const int gid = lane >> 2;
    const int tig = lane & 3;
    #pragma unroll
    for (int mi = 0; mi < 2; mi++) {
        #pragma unroll
        for (int half = 0; half < 2; half++) {
            int row = blockRow + warpRow * 32 + mi * 16 + gid + half * 8;
            if (row >= NN) continue;
            #pragma unroll
            for (int ni = 0; ni < 4; ni++) {
                int col  = warpCol * 32 + ni * 8 + tig * 2;
                int gcol = colGrp + col;
                float v0 = acc[mi][ni][half * 2]     + bias[gcol];
                float v1 = acc[mi][ni][half * 2 + 1] + bias[gcol + 1];
                if (mode == 0) {
                    float2 o = make_float2(1.f / (1.f + expf(-v0)),
                                           1.f / (1.f + expf(-v1)));
                    *(float2*)(out0 + (size_t)row * 256 + gcol) = o;
                } else if (mode == 1) {
                    float2 z  = *(const float2*)(Zbuf + (size_t)row * 256 + gcol);
                    float2 hs = *(const float2*)(Hs + (size_t)row * 128 + gcol);
                    float h0 = z.x * hs.x + (1.f - z.x) * tanhf(v0);
                    float h1 = z.y * hs.y + (1.f - z.y) * tanhf(v1);
                    *(float2*)(out0 + (size_t)row * 128 + gcol) = make_float2(h0, h1);
                    *(float2*)(out1 + (size_t)row * 128 + gcol) =
                        make_float2(fmaxf(h0, 0.f), fmaxf(h1, 0.f));
                } else {
                    *(float2*)(out0 + (size_t)row * 64 + gcol) = make_float2(v0, v1);
                }
            }
        }
    }
}

// ---------------- launch ------------------------------------------------------
extern "C" void kernel_launch(void* const* d_in, const int* in_sizes, int n_in,
                              void* d_out, int out_size) {
    const int*   ei  = (const int*)d_in[0];
    const float* X   = (const float*)d_in[1];
    const float* ew  = (const float*)d_in[2];
    const float* Hs  = (const float*)d_in[3];
    const float* Wz  = (const float*)d_in[4];
    const float* bz  = (const float*)d_in[5];
    const float* Wr  = (const float*)d_in[6];
    const float* br  = (const float*)d_in[7];
    const float* Wh  = (const float*)d_in[8];
    const float* bh  = (const float*)d_in[9];
    const float* Lz  = (const float*)d_in[10];
    const float* Lzb = (const float*)d_in[11];
    const float* Lr  = (const float*)d_in[12];
    const float* Lrb = (const float*)d_in[13];
    const float* Lh  = (const float*)d_in[14];
    const float* Lhb = (const float*)d_in[15];
    const float* LoW = (const float*)d_in[16];
    const float* LoB = (const float*)d_in[17];

    const int E = in_sizes[2];

    float* out   = (float*)d_out;
    float* out_y = out;                       // N x 64
    float* out_h = out + (size_t)NN * FF;     // N x 128

    void *pAX, *pZR, *pReluh, *pBp, *pBcat;
    cudaGetSymbolAddress(&pAX, g_AX);
    cudaGetSymbolAddress(&pZR, g_ZR);
    cudaGetSymbolAddress(&pReluh, g_reluh);
    cudaGetSymbolAddress(&pBp, g_Bp);
    cudaGetSymbolAddress(&pBcat, g_bcat);

    const size_t sm192 = (size_t)(128 * 96 + 64 * 192) * 4;   // 98304
    const size_t sm128 = (size_t)(128 * 64 + 64 * 128) * 4;   // 65536
    cudaFuncSetAttribute(gemm_tc<64, 128>, cudaFuncAttributeMaxDynamicSharedMemorySize,
                         (int)sm192);
    cudaFuncSetAttribute(gemm_tc<128, 0>, cudaFuncAttributeMaxDynamicSharedMemorySize,
                         (int)sm128);

    // 1. pack weights (permuted tf32 B + biases)
    k_pack<<<(384 * 192 + 64 * 128 + 384 + 255) / 256, 256>>>(
        Wz, bz, Wr, br, Wh, bh, Lz, Lzb, Lr, Lrb, Lh, Lhb, LoW);
    // 2. degree
    k_deg<<<(E + 255) / 256, 256>>>(ei, ew, E);
    // 3. dinv + AX self-loop init (+ deg reset for next replay)
    k_dinvax<<<(NN * 16 + 255) / 256, 256>>>(X);
    // 4. aggregate X once (GCN linearity)
    k_agg<<<(E * 16 + 255) / 256, 256>>>(ei, ew, X, E);

    const int gridM = (NN + 127) / 128;  // 391

    // 5. GEMM1: [AX | Hs] @ W1 -> sigmoid -> Z,R  (256 cols = 4 col-blocks)
    gemm_tc<64, 128><<<dim3(gridM, 4), 256, sm192>>>(
        (const float*)pAX, Hs, nullptr,
        (const uint32_t*)pBp, (const float*)pBcat, 0,
        nullptr, nullptr, (float*)pZR, nullptr);
    // 6. GEMM2: [AX | Hs*R] @ W2 -> tanh -> GRU -> h, relu(h)  (128 cols)
    gemm_tc<64, 128><<<dim3(gridM, 2), 256, sm192>>>(
        (const float*)pAX, Hs, (const float*)pZR,
        (const uint32_t*)pBp + 4 * 12288, (const float*)pBcat + 256, 1,
        (const float*)pZR, Hs, out_h, (float*)pReluh);
    // 7. GEMM3: relu(h) @ Lout + b -> y  (64 cols)
    gemm_tc<128, 0><<<dim3(gridM, 1), 256, sm128>>>(
        (const float*)pReluh, nullptr, nullptr,
        (const uint32_t*)pBp + 6 * 12288, LoB, 2,
        nullptr, nullptr, out_y, nullptr);
}

// round 5
// speedup vs baseline: 1.9652x; 1.9652x over previous
#include <cuda_runtime.h>
#include <cuda_fp16.h>
#include <cstdint>

// Problem constants
#define NN 50000
#define FF 64
#define HH 128

// ---------------- device scratch (static globals, no cudaMalloc) -------------
__device__ float g_deg[NN];
__device__ float g_dinv[NN];
__device__ float g_AX[(size_t)NN * FF];          // aggregated X  (N x 64)
__device__ float g_ZR[(size_t)NN * 256];         // Z cols 0..127, R cols 128..255
__device__ float g_reluh[(size_t)NN * HH];       // relu(h)
// pre-permuted fp16 weights (fragment order):
//  6 gate blocks of 6144 uint32 (64 cols x 192 k) + 1 Lout block of 4096 (64 x 128)
__device__ uint32_t g_Bp[6 * 6144 + 4096];
__device__ float g_bcat[384];                    // packed gate biases

// ---------------- helpers -----------------------------------------------------
__device__ __forceinline__ uint32_t f2h2(float lo, float hi) {
    __half2 h = __floats2half2_rn(lo, hi);
    return *(uint32_t*)&h;
}
__device__ __forceinline__ void mma_f16(float* c, const uint32_t* a, const uint32_t* b) {
    asm volatile(
        "mma.sync.aligned.m16n8k16.row.col.f32.f16.f16.f32 "
        "{%0,%1,%2,%3}, {%4,%5,%6,%7}, {%8,%9}, {%0,%1,%2,%3};"
        : "+f"(c[0]), "+f"(c[1]), "+f"(c[2]), "+f"(c[3])
        : "r"(a[0]), "r"(a[1]), "r"(a[2]), "r"(a[3]), "r"(b[0]), "r"(b[1]));
}

// ---------------- weight packing ---------------------------------------------
// Gate weights folded: top64 = W_g @ Lg_top, bottom128 = Lg_bottom.
// Permuted fragment layout (uint32 index within a 64-col block):
//   ((ks*8 + c)*32 + lane)*2 + jh,  lane = gid*4 + tig
//   n = 64*blk + 8*c + gid,  k = 16*ks + 8*jh + 2*tig (+1 in high half)
__global__ void k_pack(const float* Wz, const float* bz,
                       const float* Wr, const float* br,
                       const float* Wh, const float* bh,
                       const float* Lz, const float* Lzb,
                       const float* Lr, const float* Lrb,
                       const float* Lh, const float* Lhb,
                       const float* LoW) {
    int idx = blockIdx.x * blockDim.x + threadIdx.x;
    const int TG = 6 * 6144;          // gate uint32s
    const int TL = TG + 4096;         // + Lout uint32s
    if (idx < TG) {
        int blk = idx / 6144;
        int r   = idx % 6144;
        int jh   = r & 1;
        int lane = (r >> 1) & 31;
        int cc   = (r >> 6) & 7;
        int ks   = r >> 9;            // 0..11
        int n  = blk * 64 + cc * 8 + (lane >> 2);
        int k0 = ks * 16 + jh * 8 + (lane & 3) * 2;
        int g = n >> 7;
        int jj = n & 127;
        const float* W = (g == 0) ? Wz : (g == 1) ? Wr : Wh;
        const float* L = (g == 0) ? Lz : (g == 1) ? Lr : Lh;
        float v[2];
        #pragma unroll
        for (int e = 0; e < 2; e++) {
            int k = k0 + e;
            if (k < 64) {
                float s = 0.f;
                #pragma unroll 8
                for (int t = 0; t < 128; t++) s += W[k * 128 + t] * L[t * 128 + jj];
                v[e] = s;
            } else {
                v[e] = L[(128 + (k - 64)) * 128 + jj];
            }
        }
        g_Bp[idx] = f2h2(v[0], v[1]);
    } else if (idx < TL) {
        int r = idx - TG;
        int jh   = r & 1;
        int lane = (r >> 1) & 31;
        int cc   = (r >> 6) & 7;
        int ks   = r >> 9;            // 0..7
        int n  = cc * 8 + (lane >> 2);
        int k0 = ks * 16 + jh * 8 + (lane & 3) * 2;
        g_Bp[idx] = f2h2(LoW[k0 * 64 + n], LoW[(k0 + 1) * 64 + n]);
    } else if (idx < TL + 384) {
        int j = idx - TL;
        int g = j >> 7;
        int jj = j & 127;
        const float* bg = (g == 0) ? bz : (g == 1) ? br : bh;
        const float* L  = (g == 0) ? Lz : (g == 1) ? Lr : Lh;
        const float* Lb = (g == 0) ? Lzb : (g == 1) ? Lrb : Lhb;
        float v = Lb[jj];
        for (int t = 0; t < 128; t++) v += bg[t] * L[t * 128 + jj];
        g_bcat[j] = v;
    }
}

// ---------------- degree / normalization -------------------------------------
__global__ void k_deg(const int* ei, const float* ew, int E) {
    int e = blockIdx.x * blockDim.x + threadIdx.x;
    if (e < E) atomicAdd(&g_deg[ei[E + e]], ew[e]);
}

// fused: dinv = rsqrt(deg+1), reset deg (for next graph replay), AX self-loop init
__global__ void k_dinvax(const float* __restrict__ X) {
    int tid = blockIdx.x * blockDim.x + threadIdx.x;
    if (tid >= NN * 16) return;
    int i = tid >> 4, q = tid & 15;
    float d  = g_deg[i] + 1.0f;       // self-loop weight 1
    float di = rsqrtf(d);
    __syncwarp();
    if (q == 0) { g_dinv[i] = di; g_deg[i] = 0.f; }
    float s = di * di;
    float4 x = reinterpret_cast<const float4*>(X + (size_t)i * 64)[q];
    float4 v = make_float4(x.x * s, x.y * s, x.z * s, x.w * s);
    reinterpret_cast<float4*>(g_AX + (size_t)i * 64)[q] = v;
}

// Edge scatter: AX[dst] += dinv[src]*w*dinv[dst] * X[src]   (16 threads/edge)
__global__ void k_agg(const int* __restrict__ ei, const float* __restrict__ ew,
                      const float* __restrict__ X, int E) {
    int tid = blockIdx.x * blockDim.x + threadIdx.x;
    int e = tid >> 4;
    if (e >= E) return;
    int q = tid & 15;
    int s = ei[e];
    int d = ei[E + e];
    float norm = g_dinv[s] * ew[e] * g_dinv[d];
    float4 x = reinterpret_cast<const float4*>(X + (size_t)s * 64)[q];
    float* p = g_AX + (size_t)d * 64 + q * 4;
    asm volatile("red.global.add.v4.f32 [%0], {%1, %2, %3, %4};"
                 :: "l"(p), "f"(x.x * norm), "f"(x.y * norm),
                    "f"(x.z * norm), "f"(x.w * norm)
                 : "memory");
}

// ---------------- fp16 tensor-core GEMM (R2 structure, half data) -------------
// Block tile 128 x 64, 8 warps, warp tile 32x32, BK=32 (2 k16-steps per tile).
// B whole-K in smem (vector copy of pre-permuted fp16 weights).
// mode 0: sigmoid -> out0 stride 256 (Z,R)
// mode 1: tanh + GRU -> out0 = h (stride 128), out1 = relu(h)
// mode 2: plain -> out0 stride 64
#define STR2 20     // half2 units per A smem row (stride 80B: gid*20+tig all-distinct)

template <int K1T, int K2T>
__global__ void __launch_bounds__(256)
gemm_h(const float* __restrict__ A1,
       const float* __restrict__ A2,
       const float* __restrict__ Rbuf,
       const uint32_t* __restrict__ Bp,
       const float* __restrict__ bias,
       int mode,
       const float* __restrict__ Zbuf,
       const float* __restrict__ Hs,
       float* __restrict__ out0,
       float* __restrict__ out1) {
    constexpr int K   = K1T + K2T;
    constexpr int NKS = K / 16;                 // global k16-steps
    __shared__ uint32_t As2[128 * STR2];        // half2, one BK=32 tile
    __shared__ uint32_t Bs[NKS * 512];          // whole-K permuted B (64 cols)

    const int t    = threadIdx.x;
    const int lane = t & 31;
    const int wid  = t >> 5;
    const int gid  = lane >> 2;
    const int tig  = lane & 3;
    const int warpRow = wid & 3;
    const int warpCol = wid >> 2;
    const int blockRow = blockIdx.x * 128;
    const int colGrp   = blockIdx.y * 64;

    // ---- whole-K B copy (pre-permuted fp16, straight vector copy) ----
    {
        const uint4* src = (const uint4*)(Bp + (size_t)blockIdx.y * (NKS * 512));
        uint4* dst = (uint4*)Bs;
        #pragma unroll
        for (int i = 0; i < (NKS * 128) / 256; i++) dst[t + i * 256] = src[t + i * 256];
    }

    float acc[2][4][4];
    #pragma unroll
    for (int mi = 0; mi < 2; mi++)
        #pragma unroll
        for (int ni = 0; ni < 4; ni++)
            #pragma unroll
            for (int c = 0; c < 4; c++) acc[mi][ni][c] = 0.f;

    for (int k0 = 0; k0 < K; k0 += 32) {
        // ---- A tile fill (128 x 32 half): 4 float4 loads -> 8 half2 per thread
        #pragma unroll
        for (int it = 0; it < 4; it++) {
            int i = t + it * 256;
            int row = i >> 3;          // 0..127
            int q   = i & 7;           // float4 index (k local = 4q)
            int kg  = k0 + q * 4;
            int grow = blockRow + row;
            float4 v = make_float4(0.f, 0.f, 0.f, 0.f);
            if (grow < NN) {
                if (kg < K1T) {
                    v = *(const float4*)(A1 + (size_t)grow * K1T + kg);
                } else if (K2T > 0) {
                    int k2 = kg - K1T;
                    v = *(const float4*)(A2 + (size_t)grow * K2T + k2);
                    if (Rbuf) {
                        float4 r = *(const float4*)(Rbuf + (size_t)grow * 256 + 128 + k2);
                        v.x *= r.x; v.y *= r.y; v.z *= r.z; v.w *= r.w;
                    }
                }
            }
            As2[row * STR2 + q * 2]     = f2h2(v.x, v.y);
            As2[row * STR2 + q * 2 + 1] = f2h2(v.z, v.w);
        }
        __syncthreads();

        // ---- 2 k16-steps: per step 8 A-LDS.32 + 4 B-LDS.64 + 8 MMA ----
        #pragma unroll
        for (int s = 0; s < 2; s++) {
            const int ksg = (k0 >> 4) + s;
            uint32_t a[2][4];
            #pragma unroll
            for (int mi = 0; mi < 2; mi++) {
                int r0 = warpRow * 32 + mi * 16 + gid;
                a[mi][0] = As2[r0 * STR2 + s * 8 + tig];
                a[mi][1] = As2[(r0 + 8) * STR2 + s * 8 + tig];
                a[mi][2] = As2[r0 * STR2 + s * 8 + tig + 4];
                a[mi][3] = As2[(r0 + 8) * STR2 + s * 8 + tig + 4];
            }
            uint32_t b[4][2];
            #pragma unroll
            for (int ni = 0; ni < 4; ni++) {
                int c = warpCol * 4 + ni;
                uint2 bv = *(const uint2*)&Bs[((ksg * 8 + c) * 32 + lane) * 2];
                b[ni][0] = bv.x; b[ni][1] = bv.y;
            }
            #pragma unroll
            for (int mi = 0; mi < 2; mi++)
                #pragma unroll
                for (int ni = 0; ni < 4; ni++)
                    mma_f16(acc[mi][ni], a[mi], b[ni]);
        }
        __syncthreads();
    }

    // ---- epilogue (float2-vectorized stores) ----
    #pragma unroll
    for (int mi = 0; mi < 2; mi++) {
        #pragma unroll
        for (int half = 0; half < 2; half++) {
            int row = blockRow + warpRow * 32 + mi * 16 + gid + half * 8;
            if (row >= NN) continue;
            #pragma unroll
            for (int ni = 0; ni < 4; ni++) {
                int col  = warpCol * 32 + ni * 8 + tig * 2;
                int gcol = colGrp + col;
                float v0 = acc[mi][ni][half * 2]     + bias[gcol];
                float v1 = acc[mi][ni][half * 2 + 1] + bias[gcol + 1];
                if (mode == 0) {
                    float2 o = make_float2(1.f / (1.f + expf(-v0)),
                                           1.f / (1.f + expf(-v1)));
                    *(float2*)(out0 + (size_t)row * 256 + gcol) = o;
                } else if (mode == 1) {
                    float2 z  = *(const float2*)(Zbuf + (size_t)row * 256 + gcol);
                    float2 hs = *(const float2*)(Hs + (size_t)row * 128 + gcol);
                    float h0 = z.x * hs.x + (1.f - z.x) * tanhf(v0);
                    float h1 = z.y * hs.y + (1.f - z.y) * tanhf(v1);
                    *(float2*)(out0 + (size_t)row * 128 + gcol) = make_float2(h0, h1);
                    *(float2*)(out1 + (size_t)row * 128 + gcol) =
                        make_float2(fmaxf(h0, 0.f), fmaxf(h1, 0.f));
                } else {
                    *(float2*)(out0 + (size_t)row * 64 + gcol) = make_float2(v0, v1);
                }
            }
        }
    }
}

// ---------------- launch ------------------------------------------------------
extern "C" void kernel_launch(void* const* d_in, const int* in_sizes, int n_in,
                              void* d_out, int out_size) {
    const int*   ei  = (const int*)d_in[0];
    const float* X   = (const float*)d_in[1];
    const float* ew  = (const float*)d_in[2];
    const float* Hs  = (const float*)d_in[3];
    const float* Wz  = (const float*)d_in[4];
    const float* bz  = (const float*)d_in[5];
    const float* Wr  = (const float*)d_in[6];
    const float* br  = (const float*)d_in[7];
    const float* Wh  = (const float*)d_in[8];
    const float* bh  = (const float*)d_in[9];
    const float* Lz  = (const float*)d_in[10];
    const float* Lzb = (const float*)d_in[11];
    const float* Lr  = (const float*)d_in[12];
    const float* Lrb = (const float*)d_in[13];
    const float* Lh  = (const float*)d_in[14];
    const float* Lhb = (const float*)d_in[15];
    const float* LoW = (const float*)d_in[16];
    const float* LoB = (const float*)d_in[17];

    const int E = in_sizes[2];

    float* out   = (float*)d_out;
    float* out_y = out;                       // N x 64
    float* out_h = out + (size_t)NN * FF;     // N x 128

    void *pAX, *pZR, *pReluh, *pBp, *pBcat;
    cudaGetSymbolAddress(&pAX, g_AX);
    cudaGetSymbolAddress(&pZR, g_ZR);
    cudaGetSymbolAddress(&pReluh, g_reluh);
    cudaGetSymbolAddress(&pBp, g_Bp);
    cudaGetSymbolAddress(&pBcat, g_bcat);

    // 1. pack weights (fold GCN weights, permute to fp16 fragment order)
    k_pack<<<(6 * 6144 + 4096 + 384 + 255) / 256, 256>>>(
        Wz, bz, Wr, br, Wh, bh, Lz, Lzb, Lr, Lrb, Lh, Lhb, LoW);
    // 2. degree
    k_deg<<<(E + 255) / 256, 256>>>(ei, ew, E);
    // 3. dinv + AX self-loop init (+ deg reset for next replay)
    k_dinvax<<<(NN * 16 + 255) / 256, 256>>>(X);
    // 4. aggregate X once (GCN linearity)
    k_agg<<<(E * 16 + 255) / 256, 256>>>(ei, ew, X, E);

    const int gridM = (NN + 127) / 128;  // 391

    // 5. GEMM1: [AX | Hs] @ W1 -> sigmoid -> Z,R  (256 cols = 4 col-blocks)
    gemm_h<64, 128><<<dim3(gridM, 4), 256>>>(
        (const float*)pAX, Hs, nullptr,
        (const uint32_t*)pBp, (const float*)pBcat, 0,
        nullptr, nullptr, (float*)pZR, nullptr);
    // 6. GEMM2: [AX | Hs*R] @ W2 -> tanh -> GRU -> h, relu(h)  (128 cols)
    gemm_h<64, 128><<<dim3(gridM, 2), 256>>>(
        (const float*)pAX, Hs, (const float*)pZR,
        (const uint32_t*)pBp + 4 * 6144, (const float*)pBcat + 256, 1,
        (const float*)pZR, Hs, out_h, (float*)pReluh);
    // 7. GEMM3: relu(h) @ Lout + b -> y  (64 cols)
    gemm_h<128, 0><<<dim3(gridM, 1), 256>>>(
        (const float*)pReluh, nullptr, nullptr,
        (const uint32_t*)pBp + 6 * 6144, LoB, 2,
        nullptr, nullptr, out_y, nullptr);
}